// round 5
// baseline (speedup 1.0000x reference)
#include <cuda_runtime.h>
#include <cstdint>

#define EMB     300
#define EMB4    75
#define TASKS   12
#define ROWB    12                      // rows per pipeline chunk
#define CHUNKB  (ROWB * EMB * 4)        // 14400 bytes (16B multiple)
#define NBUF    4
#define NG      8                       // graphs per CTA
#define THREADS 160                     // 5 warps; 150 loader lanes

__device__ int g_starts[16385 * 2];

// ---------------------------------------------------------------------------
// starts[g] = lower_bound(sorted batch, g). int32/int64 detected via word[N-1]
// (int64 high word of last element is 0; int32 last element is max id > 0).
// ---------------------------------------------------------------------------
__global__ void starts_kernel(const void* __restrict__ batch, int N, int G) {
    int i = blockIdx.x * blockDim.x + threadIdx.x;
    if (i >= N) return;
    const int* b32 = (const int*)batch;
    int is64 = (b32[N - 1] == 0);

    long long cur, prev;
    if (is64) {
        const long long* b64 = (const long long*)batch;
        cur  = b64[i];
        prev = (i > 0) ? b64[i - 1] : -1;
    } else {
        cur  = b32[i];
        prev = (i > 0) ? b32[i - 1] : -1;
    }
    for (long long g = prev + 1; g <= cur; ++g) {
        if (g >= 0 && g <= (long long)G) g_starts[g] = i;
    }
    if (i == N - 1) {
        for (long long g = cur + 1; g <= (long long)G; ++g) g_starts[g] = N;
    }
}

__device__ __forceinline__ void facc(float4& a, const float4 v) {
    a.x += v.x; a.y += v.y; a.z += v.z; a.w += v.w;
}

// ---------------------------------------------------------------------------
// CTA handles NG consecutive graphs: one continuous cp.async.bulk stream over
// their contiguous row range; per-graph finalize (2 syncs + fused head) at
// boundaries inside the consumer loop. No pipeline drain between graphs.
// ---------------------------------------------------------------------------
__global__ __launch_bounds__(THREADS)
void pool_multi_kernel(const float* __restrict__ x,
                       const float* __restrict__ W,
                       const float* __restrict__ b,
                       float* __restrict__ out, int G) {
    __shared__ alignas(16) float4 buf[NBUF][ROWB * EMB4];
    __shared__ alignas(8)  unsigned long long mbar[NBUF];
    __shared__ alignas(16) float4 sums4[150];
    __shared__ alignas(16) float  fin[EMB];

    int t  = threadIdx.x;
    int g0 = blockIdx.x * NG;
    int gcnt = G - g0; if (gcnt > NG) gcnt = NG;

    int base       = g_starts[g0];
    int rows_total = g_starts[g0 + gcnt] - base;
    int nchunks    = (rows_total + ROWB - 1) / ROWB;

    uint32_t mb0 = (uint32_t)__cvta_generic_to_shared(&mbar[0]);
    if (t == 0) {
        #pragma unroll
        for (int s = 0; s < NBUF; ++s)
            asm volatile("mbarrier.init.shared::cta.b64 [%0], 1;"
                         :: "r"(mb0 + 8u * s) : "memory");
    }
    __syncthreads();

    const char* src_base = (const char*)(x + (size_t)base * EMB);

    // prologue: issue up to NBUF-1 chunks ahead
    if (t == 0) {
        int pre = nchunks < (NBUF - 1) ? nchunks : (NBUF - 1);
        for (int k = 0; k < pre; ++k) {
            int r0 = k * ROWB;
            int rc = rows_total - r0; if (rc > ROWB) rc = ROWB;
            uint32_t bytes = (uint32_t)rc * (EMB * 4);
            uint32_t mb    = mb0 + 8u * k;
            uint32_t dst   = (uint32_t)__cvta_generic_to_shared(&buf[k][0]);
            const char* sp = src_base + (size_t)r0 * (EMB * 4);
            asm volatile("mbarrier.arrive.expect_tx.shared::cta.b64 _, [%0], %1;"
                         :: "r"(mb), "r"(bytes) : "memory");
            asm volatile("cp.async.bulk.shared::cta.global.mbarrier::complete_tx::bytes [%0], [%1], %2, [%3];"
                         :: "r"(dst), "l"(sp), "r"(bytes), "r"(mb) : "memory");
        }
    }

    int c = t % EMB4;            // float4 column (t < 150)
    int p = t / EMB4;            // row parity
    int wid = t >> 5, lane = t & 31;
    float4 acc = make_float4(0.f, 0.f, 0.f, 0.f);

    int gi = 0;
    int gstart = 0;                                        // first row of cur graph
    int nb = (gcnt > 0) ? g_starts[g0 + 1] - base : 0;     // cur graph end row

    for (int k = 0; k < nchunks; ++k) {
        int s = k & (NBUF - 1);
        uint32_t mb = mb0 + 8u * s;
        uint32_t ph = (uint32_t)((k >> 2) & 1);

        uint32_t done;
        asm volatile("{\n\t.reg .pred p;\n\t"
                     "mbarrier.try_wait.parity.acquire.cta.shared::cta.b64 p, [%1], %2;\n\t"
                     "selp.b32 %0, 1, 0, p;\n\t}"
                     : "=r"(done) : "r"(mb), "r"(ph) : "memory");
        while (!done) {
            asm volatile("{\n\t.reg .pred p;\n\t"
                         "mbarrier.try_wait.parity.acquire.cta.shared::cta.b64 p, [%1], %2, 0x989680;\n\t"
                         "selp.b32 %0, 1, 0, p;\n\t}"
                         : "=r"(done) : "r"(mb), "r"(ph) : "memory");
        }

        int rbase = k * ROWB;
        int rend  = rbase + ROWB; if (rend > rows_total) rend = rows_total;
        const float4* bp = &buf[s][0];

        int pos = rbase;
        while (pos < rend) {                       // uniform control flow
            int stop = nb < rend ? nb : rend;
            if (t < 150) {
                for (int r = pos + p; r < stop; r += 2)
                    facc(acc, bp[(r - rbase) * EMB4 + c]);
            }
            if (stop == nb) {
                // ---- finalize graph g0+gi ----
                if (t < 150) sums4[t] = acc;
                __syncthreads();
                if (t < EMB4) {
                    float4 a0 = sums4[t], a1 = sums4[t + EMB4];
                    ((float4*)fin)[t] = make_float4(a0.x + a1.x, a0.y + a1.y,
                                                    a0.z + a1.z, a0.w + a1.w);
                }
                __syncthreads();
                float inv = 1.0f / fmaxf((float)(nb - gstart), 1.0f);
                for (int task = wid; task < TASKS; task += 5) {
                    const float* wr = W + task * EMB;
                    float a = 0.f;
                    #pragma unroll
                    for (int d = lane; d < EMB; d += 32) a += fin[d] * __ldg(&wr[d]);
                    #pragma unroll
                    for (int o = 16; o; o >>= 1) a += __shfl_xor_sync(0xffffffffu, a, o);
                    if (lane == 0) out[(size_t)(g0 + gi) * TASKS + task] = a * inv + b[task];
                }
                acc = make_float4(0.f, 0.f, 0.f, 0.f);
                gstart = nb;
                ++gi;
                nb = (gi < gcnt) ? g_starts[g0 + gi + 1] - base : 0x7fffffff;
            }
            pos = stop;
        }
        __syncthreads();   // chunk s fully consumed -> safe to refill

        if (t == 0 && k + (NBUF - 1) < nchunks) {
            asm volatile("fence.proxy.async.shared::cta;" ::: "memory");
            int kk = k + (NBUF - 1);
            int r0 = kk * ROWB;
            int rc = rows_total - r0; if (rc > ROWB) rc = ROWB;
            uint32_t bytes = (uint32_t)rc * (EMB * 4);
            uint32_t mbn   = mb0 + 8u * (kk & (NBUF - 1));
            uint32_t dst   = (uint32_t)__cvta_generic_to_shared(&buf[kk & (NBUF - 1)][0]);
            const char* sp = src_base + (size_t)r0 * (EMB * 4);
            asm volatile("mbarrier.arrive.expect_tx.shared::cta.b64 _, [%0], %1;"
                         :: "r"(mbn), "r"(bytes) : "memory");
            asm volatile("cp.async.bulk.shared::cta.global.mbarrier::complete_tx::bytes [%0], [%1], %2, [%3];"
                         :: "r"(dst), "l"(sp), "r"(bytes), "r"(mbn) : "memory");
        }
    }

    // trailing empty graphs (boundaries at rows_total not crossed in-loop)
    while (gi < gcnt) {
        for (int task = wid; task < TASKS; task += 5) {
            if (lane == 0) out[(size_t)(g0 + gi) * TASKS + task] = b[task];
        }
        ++gi;
    }
}

// ---------------------------------------------------------------------------
extern "C" void kernel_launch(void* const* d_in, const int* in_sizes, int n_in,
                              void* d_out, int out_size) {
    const float* x     = (const float*)d_in[0];
    const void*  batch = d_in[1];
    const float* W     = (const float*)d_in[2];
    const float* b     = (const float*)d_in[3];
    float*       out   = (float*)d_out;

    int N = in_sizes[1];
    int G = out_size / TASKS;

    starts_kernel<<<(N + 255) / 256, 256>>>(batch, N, G);
    pool_multi_kernel<<<(G + NG - 1) / NG, THREADS>>>(x, W, b, out, G);
}

// round 7
// speedup vs baseline: 1.0295x; 1.0295x over previous
#include <cuda_runtime.h>
#include <cstdint>

#define EMB     300
#define EMB4    75
#define TASKS   12
#define ROWB    8                       // rows per pipeline chunk
#define NBUF    4
#define THREADS 160                     // 5 warps; 150 loader lanes
#define NCTA    592                     // 4 CTAs/SM x 148 SMs = one wave

__device__ int g_starts[16385 * 2];

// ---------------------------------------------------------------------------
// starts[g] = lower_bound(sorted batch, g). int32/int64 detected via word[N-1]
// (int64 high word of last element is 0; int32 last element is max id > 0).
// ---------------------------------------------------------------------------
__global__ void starts_kernel(const void* __restrict__ batch, int N, int G) {
    int i = blockIdx.x * blockDim.x + threadIdx.x;
    if (i >= N) return;
    const int* b32 = (const int*)batch;
    int is64 = (b32[N - 1] == 0);

    long long cur, prev;
    if (is64) {
        const long long* b64 = (const long long*)batch;
        cur  = b64[i];
        prev = (i > 0) ? b64[i - 1] : -1;
    } else {
        cur  = b32[i];
        prev = (i > 0) ? b32[i - 1] : -1;
    }
    for (long long g = prev + 1; g <= cur; ++g) {
        if (g >= 0 && g <= (long long)G) g_starts[g] = i;
    }
    if (i == N - 1) {
        for (long long g = cur + 1; g <= (long long)G; ++g) g_starts[g] = N;
    }
}

__device__ __forceinline__ void facc(float4& a, const float4 v) {
    a.x += v.x; a.y += v.y; a.z += v.z; a.w += v.w;
}

// ---------------------------------------------------------------------------
// Persistent single-wave CTA: owns a contiguous range of ~G/592 graphs, one
// continuous cp.async.bulk stream over their rows. Per-graph finalize:
// register-space head partials -> double-buffered SMEM -> ONE sync -> 5-warp
// reduction. Post-loop finalize catches boundaries coinciding with the last
// chunk end (the round-6 bug).
// ---------------------------------------------------------------------------
__global__ __launch_bounds__(THREADS)
void pool_pers_kernel(const float* __restrict__ x,
                      const float* __restrict__ W,
                      const float* __restrict__ b,
                      float* __restrict__ out, int G) {
    __shared__ alignas(16) float4 buf[NBUF][ROWB * EMB4];
    __shared__ alignas(8)  unsigned long long mbar[NBUF];
    __shared__ alignas(16) float sh_part[2][TASKS * THREADS];

    int t = threadIdx.x;
    int g0 = (int)(((long long)blockIdx.x * G) / NCTA);
    int g1 = (int)(((long long)(blockIdx.x + 1) * G) / NCTA);
    int gcnt = g1 - g0;
    if (gcnt <= 0) return;

    int base       = g_starts[g0];
    int rows_total = g_starts[g1] - base;
    int nchunks    = (rows_total + ROWB - 1) / ROWB;

    uint32_t mb0 = (uint32_t)__cvta_generic_to_shared(&mbar[0]);
    if (t == 0) {
        #pragma unroll
        for (int s = 0; s < NBUF; ++s)
            asm volatile("mbarrier.init.shared::cta.b64 [%0], 1;"
                         :: "r"(mb0 + 8u * s) : "memory");
    }
    __syncthreads();

    const char* src_base = (const char*)(x + (size_t)base * EMB);

    if (t == 0) {
        int pre = nchunks < (NBUF - 1) ? nchunks : (NBUF - 1);
        for (int k = 0; k < pre; ++k) {
            int r0 = k * ROWB;
            int rc = rows_total - r0; if (rc > ROWB) rc = ROWB;
            uint32_t bytes = (uint32_t)rc * (EMB * 4);
            uint32_t mb    = mb0 + 8u * k;
            uint32_t dst   = (uint32_t)__cvta_generic_to_shared(&buf[k][0]);
            const char* sp = src_base + (size_t)r0 * (EMB * 4);
            asm volatile("mbarrier.arrive.expect_tx.shared::cta.b64 _, [%0], %1;"
                         :: "r"(mb), "r"(bytes) : "memory");
            asm volatile("cp.async.bulk.shared::cta.global.mbarrier::complete_tx::bytes [%0], [%1], %2, [%3];"
                         :: "r"(dst), "l"(sp), "r"(bytes), "r"(mb) : "memory");
        }
    }

    int c = t % EMB4;            // float4 column (t < 150)
    int p = t / EMB4;            // row parity (0/1 for t<150; 2 for tail lanes)
    int wid = t >> 5, lane = t & 31;
    const float4* __restrict__ W4 = (const float4*)W;
    float4 acc = make_float4(0.f, 0.f, 0.f, 0.f);

    int gi = 0;
    int gstart = 0;                       // first row of current graph (rel.)
    int nb = g_starts[g0 + 1] - base;     // current graph end row (rel.)

    // finalize current graph ending at end_row. Uniform control flow required.
    auto do_finalize = [&](int end_row) {
        int pb = gi & 1;
        #pragma unroll
        for (int task = 0; task < TASKS; ++task) {
            float4 w4 = __ldg(&W4[task * EMB4 + c]);
            sh_part[pb][task * THREADS + t] =
                acc.x * w4.x + acc.y * w4.y + acc.z * w4.z + acc.w * w4.w;
        }
        __syncthreads();
        float inv = 1.0f / fmaxf((float)(end_row - gstart), 1.0f);
        for (int task = wid; task < TASKS; task += 5) {
            const float* sp = &sh_part[pb][task * THREADS];
            float a = sp[lane] + sp[lane + 32] + sp[lane + 64]
                    + sp[lane + 96] + sp[lane + 128];
            #pragma unroll
            for (int o = 16; o; o >>= 1) a += __shfl_xor_sync(0xffffffffu, a, o);
            if (lane == 0)
                out[(size_t)(g0 + gi) * TASKS + task] = a * inv + __ldg(&b[task]);
        }
        acc = make_float4(0.f, 0.f, 0.f, 0.f);
        gstart = end_row;
        ++gi;
        nb = (gi < gcnt) ? g_starts[g0 + gi + 1] - base : 0x7fffffff;
    };

    for (int k = 0; k < nchunks; ++k) {
        int s = k & (NBUF - 1);
        uint32_t mb = mb0 + 8u * s;
        uint32_t ph = (uint32_t)((k >> 2) & 1);

        uint32_t done;
        asm volatile("{\n\t.reg .pred p;\n\t"
                     "mbarrier.try_wait.parity.acquire.cta.shared::cta.b64 p, [%1], %2;\n\t"
                     "selp.b32 %0, 1, 0, p;\n\t}"
                     : "=r"(done) : "r"(mb), "r"(ph) : "memory");
        while (!done) {
            asm volatile("{\n\t.reg .pred p;\n\t"
                         "mbarrier.try_wait.parity.acquire.cta.shared::cta.b64 p, [%1], %2, 0x989680;\n\t"
                         "selp.b32 %0, 1, 0, p;\n\t}"
                         : "=r"(done) : "r"(mb), "r"(ph) : "memory");
        }

        int rbase = k * ROWB;
        int rend  = rbase + ROWB; if (rend > rows_total) rend = rows_total;
        const float4* bp = &buf[s][0];

        if (nb >= rend && rend == rbase + ROWB) {
            // fast path: whole (full) chunk inside current graph
            if (t < 150) {
                float4 v0 = bp[(0 + p) * EMB4 + c];
                float4 v1 = bp[(2 + p) * EMB4 + c];
                float4 v2 = bp[(4 + p) * EMB4 + c];
                float4 v3 = bp[(6 + p) * EMB4 + c];
                facc(acc, v0); facc(acc, v1); facc(acc, v2); facc(acc, v3);
            }
        } else {
            int pos = rbase;
            while (pos < rend) {
                int stop = nb < rend ? nb : rend;
                if (t < 150) {
                    for (int r = pos; r < stop; ++r) {
                        if (((r - rbase) & 1) == p)
                            facc(acc, bp[(r - rbase) * EMB4 + c]);
                    }
                }
                if (stop == nb) do_finalize(nb);
                pos = stop;
            }
        }
        __syncthreads();   // chunk s consumed -> refill safe

        if (t == 0 && k + (NBUF - 1) < nchunks) {
            asm volatile("fence.proxy.async.shared::cta;" ::: "memory");
            int kk = k + (NBUF - 1);
            int r0 = kk * ROWB;
            int rc = rows_total - r0; if (rc > ROWB) rc = ROWB;
            uint32_t bytes = (uint32_t)rc * (EMB * 4);
            uint32_t mbn   = mb0 + 8u * (kk & (NBUF - 1));
            uint32_t dst   = (uint32_t)__cvta_generic_to_shared(&buf[kk & (NBUF - 1)][0]);
            const char* sp = src_base + (size_t)r0 * (EMB * 4);
            asm volatile("mbarrier.arrive.expect_tx.shared::cta.b64 _, [%0], %1;"
                         :: "r"(mbn), "r"(bytes) : "memory");
            asm volatile("cp.async.bulk.shared::cta.global.mbarrier::complete_tx::bytes [%0], [%1], %2, [%3];"
                         :: "r"(dst), "l"(sp), "r"(bytes), "r"(mbn) : "memory");
        }
    }

    // FIX (round 6 bug): a graph whose boundary coincides with the final chunk
    // end is still open here — finalize it with its accumulated data.
    if (gi < gcnt) do_finalize(rows_total);

    // any graphs after that are empty: mean = 0 -> out = bias
    while (gi < gcnt) {
        if (t < TASKS) out[(size_t)(g0 + gi) * TASKS + t] = __ldg(&b[t]);
        ++gi;
    }
}

// ---------------------------------------------------------------------------
extern "C" void kernel_launch(void* const* d_in, const int* in_sizes, int n_in,
                              void* d_out, int out_size) {
    const float* x     = (const float*)d_in[0];
    const void*  batch = d_in[1];
    const float* W     = (const float*)d_in[2];
    const float* b     = (const float*)d_in[3];
    float*       out   = (float*)d_out;

    int N = in_sizes[1];
    int G = out_size / TASKS;

    starts_kernel<<<(N + 255) / 256, 256>>>(batch, N, G);
    pool_pers_kernel<<<NCTA, THREADS>>>(x, W, b, out, G);
}